// round 11
// baseline (speedup 1.0000x reference)
#include <cuda_runtime.h>
#include <mma.h>

using namespace nvcuda;

// ---------------------------------------------------------------------------
// HGTransformerLayer — tf32 tensor-core, round 11.
//   k[b,n] = Kbase[n] + KE[t], v[b,n] = Vbase[n] + VE[t]  (t in {0,1})
//   scores = Q·Kbase^T + qe[row][t];  out = P·Vbase + w0·VE0 + w1·VE1
// KEY: wmma fragments load DIRECTLY from global (g_K/g_V/A/W are already in
// fragment-compatible layouts) — no smem staging, no mainloop barriers.
// GEMMs: 3xTF32, CTA 32x128, warp 16x32, 0 smem in mainloop, 1 sync total.
// Attention: 16 rows/CTA, 2 CTAs/SM, 4 barriers total, single-pass softmax.
// ---------------------------------------------------------------------------

#define SCALE_Q 0.17677669529663687f  // 1/sqrt(32)

__device__ float g_Q[1024 * 256];   // [h][b][32], scaled, tf32-rounded
__device__ float g_K[1024 * 256];   // [h][n][32], tf32-rounded
__device__ float g_V[1024 * 256];   // [h][n][32], tf32-rounded
__device__ float g_KE[2 * 256];
__device__ float g_VE[2 * 256];
__device__ float g_AO[1024 * 256];  // row-major [b][256]
__device__ unsigned g_mba2[1024 * 32];  // adjacency bits: [row][n/32]
__device__ unsigned g_mbt2[1024 * 32];  // edge-type bits

typedef wmma::fragment<wmma::matrix_a, 16, 16, 8, wmma::precision::tf32, wmma::row_major> FragA;
typedef wmma::fragment<wmma::matrix_b, 16, 16, 8, wmma::precision::tf32, wmma::col_major> FragBc;
typedef wmma::fragment<wmma::matrix_b, 16, 16, 8, wmma::precision::tf32, wmma::row_major> FragBr;
typedef wmma::fragment<wmma::accumulator, 16, 16, 8, float> FragC;

template <typename F>
__device__ __forceinline__ void split_tf32(const F& raw, F& hi, F& lo) {
#pragma unroll
    for (int i = 0; i < raw.num_elements; ++i) {
        float h = wmma::__float_to_tf32(raw.x[i]);
        hi.x[i] = h;
        lo.x[i] = wmma::__float_to_tf32(raw.x[i] - h);
    }
}

// ---------------------------------------------------------------------------
// 3xTF32 GEMM: C[32x128 tile] = (A[.,256] @ W[256,256]^T + bias) * scale
// 256 threads, 8 warps (2 row x 4 col), warp tile 16x32.
// Fragments load DIRECTLY from global; no smem in the mainloop, no syncs.
// ---------------------------------------------------------------------------
__device__ __forceinline__ void gemm_body(const float* __restrict__ A,
                                          const float* __restrict__ W,
                                          const float* __restrict__ bias,
                                          float* __restrict__ C, float scale,
                                          bool headmode, int m0, int n0)
{
    __shared__ float sEp[8 * 576];   // 16x32 (+pad 36) per warp

    const int tid = threadIdx.x;
    const int warp = tid >> 5;
    const int mb = m0 + (warp >> 2) * 16;       // warp row base
    const int nb = n0 + (warp & 3) * 32;        // warp col base

    const float* aP  = A + mb * 256;
    const float* bP0 = W + nb * 256;
    const float* bP1 = W + (nb + 16) * 256;

    FragC c0, c1;
    wmma::fill_fragment(c0, 0.f);
    wmma::fill_fragment(c1, 0.f);

#pragma unroll 4
    for (int k = 0; k < 256; k += 8) {
        FragA araw, ahi, alo;
        wmma::load_matrix_sync(araw, aP + k, 256);
        split_tf32(araw, ahi, alo);

        FragBc braw, bhi, blo;
        wmma::load_matrix_sync(braw, bP0 + k, 256);
        split_tf32(braw, bhi, blo);
        wmma::mma_sync(c0, ahi, bhi, c0);
        wmma::mma_sync(c0, ahi, blo, c0);
        wmma::mma_sync(c0, alo, bhi, c0);

        wmma::load_matrix_sync(braw, bP1 + k, 256);
        split_tf32(braw, bhi, blo);
        wmma::mma_sync(c1, ahi, bhi, c1);
        wmma::mma_sync(c1, ahi, blo, c1);
        wmma::mma_sync(c1, alo, bhi, c1);
    }

    wmma::store_matrix_sync(&sEp[warp * 576 + 0],  c0, 36, wmma::mem_row_major);
    wmma::store_matrix_sync(&sEp[warp * 576 + 16], c1, 36, wmma::mem_row_major);
    __syncthreads();

#pragma unroll
    for (int i = 0; i < 16; ++i) {
        int o = tid + i * 256;               // 4096 outputs, 32x128 tile
        int lm = o >> 7, ln = o & 127;
        int wsrc = (lm >> 4) * 4 + (ln >> 5);
        float val = sEp[wsrc * 576 + (lm & 15) * 36 + (ln & 31)];
        int m = m0 + lm, n = n0 + ln;
        val = (val + __ldg(&bias[n])) * scale;
        if (headmode) {
            val = wmma::__float_to_tf32(val);   // pre-rounded for attn MMAs
            C[(n >> 5) * 32768 + m * 32 + (n & 31)] = val;
        } else {
            C[m * 256 + n] = val;
        }
    }
}

// ---------------------------------------------------------------------------
// prep: blocks [0,128): mask pack (thread-per-word, int4 loads, MLP~16);
//       [128,320): qkv GEMMs (64 each); [320,324): edge projections.
// ---------------------------------------------------------------------------
__global__ __launch_bounds__(256)
void prep_kernel(const float* __restrict__ hT, const float* __restrict__ hN,
                 const float* __restrict__ Wq, const float* __restrict__ bq,
                 const float* __restrict__ Wk, const float* __restrict__ bk,
                 const float* __restrict__ Wv, const float* __restrict__ bv,
                 const float* __restrict__ E,
                 const int* __restrict__ adj, const int* __restrict__ et)
{
    const int b = blockIdx.x;
    if (b < 128) {
        const int gw = b * 256 + threadIdx.x;       // word index 0..32767
        const int4* ap = reinterpret_cast<const int4*>(adj) + gw * 8;
        const int4* tp = reinterpret_cast<const int4*>(et) + gw * 8;
        unsigned va = 0, vt = 0;
#pragma unroll
        for (int i = 0; i < 8; ++i) {
            int4 xa = __ldg(ap + i);
            int4 xt = __ldg(tp + i);
            va |= (unsigned)(xa.x != 0) << (i * 4 + 0);
            va |= (unsigned)(xa.y != 0) << (i * 4 + 1);
            va |= (unsigned)(xa.z != 0) << (i * 4 + 2);
            va |= (unsigned)(xa.w != 0) << (i * 4 + 3);
            vt |= (unsigned)(xt.x != 0) << (i * 4 + 0);
            vt |= (unsigned)(xt.y != 0) << (i * 4 + 1);
            vt |= (unsigned)(xt.z != 0) << (i * 4 + 2);
            vt |= (unsigned)(xt.w != 0) << (i * 4 + 3);
        }
        g_mba2[gw] = va;
        g_mbt2[gw] = vt;
    } else if (b < 320) {
        const int bb = b - 128;
        const int mat = bb / 64;              // 0..2
        const int idx = bb & 63;
        const int m0 = (idx & 31) * 32;
        const int n0 = (idx >> 5) * 128;
        if (mat == 0)      gemm_body(hT, Wq, bq, g_Q, SCALE_Q, true, m0, n0);
        else if (mat == 1) gemm_body(hN, Wk, bk, g_K, 1.f, true, m0, n0);
        else               gemm_body(hN, Wv, bv, g_V, 1.f, true, m0, n0);
    } else {
        const int bb = b - 320;
        const int t = bb & 1;
        const int isv = bb >> 1;
        const float* W = isv ? Wv : Wk;
        float* out = isv ? g_VE : g_KE;
        __shared__ float e[256];
        e[threadIdx.x] = E[t * 256 + threadIdx.x];
        __syncthreads();
        const int warp = threadIdx.x >> 5, lane = threadIdx.x & 31;
        for (int d = warp; d < 256; d += 8) {
            float acc = 0.f;
            for (int k = lane; k < 256; k += 32) acc += e[k] * W[d * 256 + k];
#pragma unroll
            for (int m = 16; m; m >>= 1) acc += __shfl_xor_sync(0xffffffffu, acc, m);
            if (lane == 0) out[t * 256 + d] = acc;
        }
    }
}

__global__ __launch_bounds__(256)
void proj_kernel(const float* __restrict__ Wo, const float* __restrict__ bo,
                 float* __restrict__ out)
{
    gemm_body(g_AO, Wo, bo, out, 1.f, false, blockIdx.x * 32, blockIdx.y * 128);
}

// ---------------------------------------------------------------------------
// Attention: grid (64 rowblocks, 8 heads), 256 thr / 8 warps, 2 CTAs/SM.
// 16 rows/CTA. S[16x1032] smem. K/V fragments load DIRECTLY from global
// ([h][n][32] => K^T col-major ld=32, V row-major ld=32). 4 barriers total.
// ---------------------------------------------------------------------------
#define SS_LD 1032
#define SMEM_ATTN_F (16 * SS_LD + 8 * 576 + 16 * 36 + 32 + 64 + 16 + 16 + 1024)

__global__ __launch_bounds__(256, 2)
void attn_kernel()
{
    extern __shared__ float sm[];
    float* sS  = sm;                          // 16512
    float* red = sS + 16 * SS_LD;             // 4608: AV partial reduce
    float* sQ  = red + 8 * 576;               // 576
    float* sqe = sQ + 16 * 36;                // 32
    float* sVE = sqe + 32;                    // 64
    float* srs = sVE + 64;                    // 16
    float* srw = srs + 16;                    // 16
    unsigned* sAdj = (unsigned*)(srw + 16);   // 512
    unsigned* sTyp = sAdj + 512;              // 512

    const int tid = threadIdx.x;
    const int h = blockIdx.y;
    const int b0 = blockIdx.x * 16;
    const int w = tid >> 5;

    // ---- stage Q, masks, VE ----
#pragma unroll
    for (int j = 0; j < 2; ++j) {
        int idx = tid + j * 256;
        sQ[(idx >> 5) * 36 + (idx & 31)] = g_Q[h * 32768 + (b0 + (idx >> 5)) * 32 + (idx & 31)];
    }
#pragma unroll
    for (int j = 0; j < 2; ++j) {
        int idx = tid + j * 256;
        sAdj[idx] = g_mba2[(b0 + (idx >> 5)) * 32 + (idx & 31)];
        sTyp[idx] = g_mbt2[(b0 + (idx >> 5)) * 32 + (idx & 31)];
    }
    if (tid < 64) sVE[tid] = g_VE[(tid >> 5) * 256 + h * 32 + (tid & 31)];
    __syncthreads();   // (1)

    // qe[row][t] = Q[row].KE[t]   (visible by sync (2))
    if (tid < 32) {
        int row = tid >> 1, t = tid & 1;
        float a = 0.f;
#pragma unroll
        for (int d = 0; d < 32; ++d) a += sQ[row * 36 + d] * g_KE[t * 256 + h * 32 + d];
        sqe[row * 2 + t] = a;
    }

    // ---- Q fragments (pre-rounded tf32) ----
    FragA af[4];
#pragma unroll
    for (int kt = 0; kt < 4; ++kt)
        wmma::load_matrix_sync(af[kt], &sQ[kt * 8], 36);

    // ---- SCORE: warp w owns n-slice [w*128, (w+1)*128); K^T direct global ----
    const float* kH = g_K + h * 32768;
#pragma unroll
    for (int f = 0; f < 8; ++f) {
        const int n0 = w * 128 + f * 16;
        const float* kbase = kH + n0 * 32;
        FragC c;
        wmma::fill_fragment(c, 0.f);
#pragma unroll
        for (int kt = 0; kt < 4; ++kt) {
            FragBc bf;
            wmma::load_matrix_sync(bf, kbase + kt * 8, 32);   // K^T col-major
            wmma::mma_sync(c, af[kt], bf, c);
        }
        wmma::store_matrix_sync(&sS[n0], c, SS_LD, wmma::mem_row_major);
    }
    __syncthreads();   // (2) all S + qe visible

    // ---- softmax: ONE pass, no max subtraction, P tf32-rounded ----
    const int row = tid >> 4, c16 = tid & 15;
    const unsigned aw0 = sAdj[row * 32 + c16 * 2 + 0];
    const unsigned aw1 = sAdj[row * 32 + c16 * 2 + 1];
    const unsigned tw0 = sTyp[row * 32 + c16 * 2 + 0];
    const unsigned tw1 = sTyp[row * 32 + c16 * 2 + 1];
    const float qe0 = sqe[row * 2], qe1 = sqe[row * 2 + 1];
    float* rowp = sS + row * SS_LD + c16 * 64;

    float rs = 0.f, rw = 0.f;
#pragma unroll
    for (int jj = 0; jj < 16; ++jj) {
        int j = (jj + c16) & 15;              // lane stagger
        float4 s = *reinterpret_cast<float4*>(&rowp[j * 4]);
        unsigned a = (j & 8) ? aw1 : aw0;
        unsigned t = (j & 8) ? tw1 : tw0;
        int bb = (j & 7) * 4;
        float p0 = ((a >> (bb + 0)) & 1u) ? __expf(s.x + (((t >> (bb + 0)) & 1u) ? qe1 : qe0)) : 0.f;
        float p1 = ((a >> (bb + 1)) & 1u) ? __expf(s.y + (((t >> (bb + 1)) & 1u) ? qe1 : qe0)) : 0.f;
        float p2 = ((a >> (bb + 2)) & 1u) ? __expf(s.z + (((t >> (bb + 2)) & 1u) ? qe1 : qe0)) : 0.f;
        float p3 = ((a >> (bb + 3)) & 1u) ? __expf(s.w + (((t >> (bb + 3)) & 1u) ? qe1 : qe0)) : 0.f;
        rs += p0 + p1 + p2 + p3;
        if ((t >> (bb + 0)) & 1u) rw += p0;
        if ((t >> (bb + 1)) & 1u) rw += p1;
        if ((t >> (bb + 2)) & 1u) rw += p2;
        if ((t >> (bb + 3)) & 1u) rw += p3;
        s.x = wmma::__float_to_tf32(p0);
        s.y = wmma::__float_to_tf32(p1);
        s.z = wmma::__float_to_tf32(p2);
        s.w = wmma::__float_to_tf32(p3);
        *reinterpret_cast<float4*>(&rowp[j * 4]) = s;
    }
#pragma unroll
    for (int m = 8; m; m >>= 1) {
        rs += __shfl_xor_sync(0xffffffffu, rs, m);
        rw += __shfl_xor_sync(0xffffffffu, rw, m);
    }
    if (c16 == 0) { srs[row] = rs; srw[row] = rw; }
    __syncthreads();   // (3) P complete

    // ---- AV: warp w owns kv slice [w*128, (w+1)*128); V direct global ----
    const float* vH = g_V + h * 32768;
    FragC oc0, oc1;
    wmma::fill_fragment(oc0, 0.f);
    wmma::fill_fragment(oc1, 0.f);
#pragma unroll
    for (int f2 = 0; f2 < 16; ++f2) {
        const int kv = w * 128 + f2 * 8;
        FragA pa;
        wmma::load_matrix_sync(pa, &sS[kv], SS_LD);
        FragBr vb0, vb1;
        wmma::load_matrix_sync(vb0, vH + kv * 32 + 0, 32);    // V row-major
        wmma::load_matrix_sync(vb1, vH + kv * 32 + 16, 32);
        wmma::mma_sync(oc0, pa, vb0, oc0);
        wmma::mma_sync(oc1, pa, vb1, oc1);
    }

    wmma::store_matrix_sync(&red[w * 576 + 0],  oc0, 36, wmma::mem_row_major);
    wmma::store_matrix_sync(&red[w * 576 + 16], oc1, 36, wmma::mem_row_major);
    __syncthreads();   // (4)

#pragma unroll
    for (int i = 0; i < 2; ++i) {
        int o = tid + i * 256;
        int r = o >> 5, d = o & 31;
        float v = 0.f;
#pragma unroll
        for (int ww = 0; ww < 8; ++ww) v += red[ww * 576 + r * 36 + d];
        float st = srs[r], w1s = srw[r];
        float inv = st > 0.f ? 1.f / st : 0.f;
        v = v * inv + (st - w1s) * inv * sVE[d] + w1s * inv * sVE[32 + d];
        g_AO[(b0 + r) * 256 + h * 32 + d] = v;
    }
}

// ---------------------------------------------------------------------------
extern "C" void kernel_launch(void* const* d_in, const int* in_sizes, int n_in,
                              void* d_out, int out_size)
{
    const float* h_target = (const float*)d_in[0];
    const float* h_neigh  = (const float*)d_in[1];
    const int*   adjacency = (const int*)d_in[2];
    const int*   edge_types = (const int*)d_in[3];
    const float* Wq = (const float*)d_in[4];
    const float* bq = (const float*)d_in[5];
    const float* Wk = (const float*)d_in[6];
    const float* bk = (const float*)d_in[7];
    const float* Wv = (const float*)d_in[8];
    const float* bv = (const float*)d_in[9];
    const float* Wo = (const float*)d_in[10];
    const float* bo = (const float*)d_in[11];
    const float* E  = (const float*)d_in[12];
    float* out = (float*)d_out;

    const int attn_smem = SMEM_ATTN_F * 4;   // 91,392 B
    static int smem_set = 0;
    if (!smem_set) {
        cudaFuncSetAttribute(attn_kernel, cudaFuncAttributeMaxDynamicSharedMemorySize,
                             attn_smem);
        smem_set = 1;
    }

    prep_kernel<<<324, 256>>>(h_target, h_neigh, Wq, bq, Wk, bk, Wv, bv, E,
                              adjacency, edge_types);
    attn_kernel<<<dim3(64, 8), 256, attn_smem>>>();
    proj_kernel<<<dim3(32, 2), 256>>>(Wo, bo, out);
}

// round 12
// speedup vs baseline: 1.4912x; 1.4912x over previous
#include <cuda_runtime.h>
#include <mma.h>

using namespace nvcuda;

// ---------------------------------------------------------------------------
// HGTransformerLayer — tf32 tensor-core, round 12.
//   k[b,n] = Kbase[n] + KE[t], v[b,n] = Vbase[n] + VE[t]  (t in {0,1})
//   scores = Q·Kbase^T + qe[row][t];  out = P·Vbase + w0·VE0 + w1·VE1
// GEMMs: smem-staged 32x64 CTA tile. QKV uses 1xTF32 (attn already consumes
// tf32-rounded Q/K/V, so extra input rounding is within budget); the output
// projection keeps 3xTF32 (its error lands directly on the output).
// Mask pack: thread-per-word int4 loads. Attention: R10 design unchanged.
// ---------------------------------------------------------------------------

#define SCALE_Q 0.17677669529663687f  // 1/sqrt(32)

__device__ float g_Q[1024 * 256];   // [h][b][32], scaled, tf32-rounded
__device__ float g_K[1024 * 256];   // [h][n][32], tf32-rounded
__device__ float g_V[1024 * 256];   // [h][n][32], tf32-rounded
__device__ float g_KE[2 * 256];
__device__ float g_VE[2 * 256];
__device__ float g_AO[1024 * 256];  // row-major [b][256]
__device__ unsigned g_mba2[1024 * 32];  // adjacency bits: [row][n/32]
__device__ unsigned g_mbt2[1024 * 32];  // edge-type bits

typedef wmma::fragment<wmma::matrix_a, 16, 16, 8, wmma::precision::tf32, wmma::row_major> FragA;
typedef wmma::fragment<wmma::matrix_b, 16, 16, 8, wmma::precision::tf32, wmma::col_major> FragBc;
typedef wmma::fragment<wmma::matrix_b, 16, 16, 8, wmma::precision::tf32, wmma::row_major> FragBr;
typedef wmma::fragment<wmma::accumulator, 16, 16, 8, float> FragC;

template <typename F>
__device__ __forceinline__ void to_tf32(F& f) {
#pragma unroll
    for (int i = 0; i < f.num_elements; ++i) f.x[i] = wmma::__float_to_tf32(f.x[i]);
}
template <typename F>
__device__ __forceinline__ void split_tf32(const F& raw, F& hi, F& lo) {
#pragma unroll
    for (int i = 0; i < raw.num_elements; ++i) {
        float h = wmma::__float_to_tf32(raw.x[i]);
        hi.x[i] = h;
        lo.x[i] = wmma::__float_to_tf32(raw.x[i] - h);
    }
}

// ---------------------------------------------------------------------------
// GEMM body: C[32x64 tile] = (A[.,256] @ W[256,256]^T + bias) * scale
// 256 threads, 8 warps (2 row x 4 col), warp tile 16x16, BK=16, smem dbuf.
// ACC3: 3xTF32 (fp32-accurate); else single tf32 pass.
// ---------------------------------------------------------------------------
template <bool ACC3>
__device__ __forceinline__ void gemm_body(const float* __restrict__ A,
                                          const float* __restrict__ W,
                                          const float* __restrict__ bias,
                                          float* __restrict__ C, float scale,
                                          bool headmode, int m0, int n0)
{
    __shared__ float sA[2][32 * 20];
    __shared__ float sB[2][64 * 20];
    __shared__ float sEp[8 * 320];

    const int tid = threadIdx.x;
    const int warp = tid >> 5;
    const int wr = warp >> 2;
    const int wc = warp & 3;

    float4 pa, pb;
    if (tid < 128)
        pa = *reinterpret_cast<const float4*>(&A[(m0 + (tid >> 2)) * 256 + (tid & 3) * 4]);
    pb = *reinterpret_cast<const float4*>(&W[(n0 + (tid >> 2)) * 256 + (tid & 3) * 4]);

    FragC c;
    wmma::fill_fragment(c, 0.f);

    for (int s = 0; s < 16; ++s) {
        float* bufA = sA[s & 1];
        float* bufB = sB[s & 1];
        if (tid < 128)
            *reinterpret_cast<float4*>(&bufA[(tid >> 2) * 20 + (tid & 3) * 4]) = pa;
        *reinterpret_cast<float4*>(&bufB[(tid >> 2) * 20 + (tid & 3) * 4]) = pb;
        __syncthreads();
        if (s < 15) {
            int k0 = (s + 1) * 16;
            if (tid < 128)
                pa = *reinterpret_cast<const float4*>(&A[(m0 + (tid >> 2)) * 256 + k0 + (tid & 3) * 4]);
            pb = *reinterpret_cast<const float4*>(&W[(n0 + (tid >> 2)) * 256 + k0 + (tid & 3) * 4]);
        }
#pragma unroll
        for (int kt = 0; kt < 2; ++kt) {
            FragA araw;
            FragBc braw;
            wmma::load_matrix_sync(araw, &bufA[wr * 16 * 20 + kt * 8], 20);
            wmma::load_matrix_sync(braw, &bufB[wc * 16 * 20 + kt * 8], 20);
            if (ACC3) {
                FragA ahi, alo;
                FragBc bhi, blo;
                split_tf32(araw, ahi, alo);
                split_tf32(braw, bhi, blo);
                wmma::mma_sync(c, ahi, bhi, c);
                wmma::mma_sync(c, ahi, blo, c);
                wmma::mma_sync(c, alo, bhi, c);
            } else {
                to_tf32(araw);
                to_tf32(braw);
                wmma::mma_sync(c, araw, braw, c);
            }
        }
        // no trailing sync: next iteration writes the other buffer
    }
    __syncthreads();
    wmma::store_matrix_sync(&sEp[warp * 320], c, 20, wmma::mem_row_major);
    __syncthreads();

#pragma unroll
    for (int i = 0; i < 8; ++i) {
        int o = tid + i * 256;
        int lm = o >> 6, ln = o & 63;
        int wsrc = (lm >> 4) * 4 + (ln >> 4);
        float val = sEp[wsrc * 320 + (lm & 15) * 20 + (ln & 15)];
        int m = m0 + lm, n = n0 + ln;
        val = (val + __ldg(&bias[n])) * scale;
        if (headmode) {
            val = wmma::__float_to_tf32(val);   // pre-rounded for attn MMAs
            C[(n >> 5) * 32768 + m * 32 + (n & 31)] = val;
        } else {
            C[m * 256 + n] = val;
        }
    }
}

// ---------------------------------------------------------------------------
// prep: blocks [0,128): mask pack (thread-per-word, int4 loads);
//       [128,512): qkv GEMMs (1xTF32); [512,516): edge projections.
// ---------------------------------------------------------------------------
__global__ __launch_bounds__(256)
void prep_kernel(const float* __restrict__ hT, const float* __restrict__ hN,
                 const float* __restrict__ Wq, const float* __restrict__ bq,
                 const float* __restrict__ Wk, const float* __restrict__ bk,
                 const float* __restrict__ Wv, const float* __restrict__ bv,
                 const float* __restrict__ E,
                 const int* __restrict__ adj, const int* __restrict__ et)
{
    const int b = blockIdx.x;
    if (b < 128) {
        const int gw = b * 256 + threadIdx.x;       // word index 0..32767
        const int4* ap = reinterpret_cast<const int4*>(adj) + gw * 8;
        const int4* tp = reinterpret_cast<const int4*>(et) + gw * 8;
        unsigned va = 0, vt = 0;
#pragma unroll
        for (int i = 0; i < 8; ++i) {
            int4 xa = __ldg(ap + i);
            int4 xt = __ldg(tp + i);
            va |= (unsigned)(xa.x != 0) << (i * 4 + 0);
            va |= (unsigned)(xa.y != 0) << (i * 4 + 1);
            va |= (unsigned)(xa.z != 0) << (i * 4 + 2);
            va |= (unsigned)(xa.w != 0) << (i * 4 + 3);
            vt |= (unsigned)(xt.x != 0) << (i * 4 + 0);
            vt |= (unsigned)(xt.y != 0) << (i * 4 + 1);
            vt |= (unsigned)(xt.z != 0) << (i * 4 + 2);
            vt |= (unsigned)(xt.w != 0) << (i * 4 + 3);
        }
        g_mba2[gw] = va;
        g_mbt2[gw] = vt;
    } else if (b < 512) {
        const int bb = b - 128;
        const int mat = bb >> 7;
        const int m0 = (bb & 31) * 32;
        const int n0 = ((bb >> 5) & 3) * 64;
        if (mat == 0)      gemm_body<false>(hT, Wq, bq, g_Q, SCALE_Q, true, m0, n0);
        else if (mat == 1) gemm_body<false>(hN, Wk, bk, g_K, 1.f, true, m0, n0);
        else               gemm_body<false>(hN, Wv, bv, g_V, 1.f, true, m0, n0);
    } else {
        const int bb = b - 512;
        const int t = bb & 1;
        const int isv = bb >> 1;
        const float* W = isv ? Wv : Wk;
        float* out = isv ? g_VE : g_KE;
        __shared__ float e[256];
        e[threadIdx.x] = E[t * 256 + threadIdx.x];
        __syncthreads();
        const int warp = threadIdx.x >> 5, lane = threadIdx.x & 31;
        for (int d = warp; d < 256; d += 8) {
            float acc = 0.f;
            for (int k = lane; k < 256; k += 32) acc += e[k] * W[d * 256 + k];
#pragma unroll
            for (int m = 16; m; m >>= 1) acc += __shfl_xor_sync(0xffffffffu, acc, m);
            if (lane == 0) out[t * 256 + d] = acc;
        }
    }
}

__global__ __launch_bounds__(256)
void proj_kernel(const float* __restrict__ Wo, const float* __restrict__ bo,
                 float* __restrict__ out)
{
    gemm_body<true>(g_AO, Wo, bo, out, 1.f, false, blockIdx.x * 32, blockIdx.y * 64);
}

// ---------------------------------------------------------------------------
// Attention: grid (64 rowblocks, 8 heads), 256 thr / 8 warps, 2 CTAs/SM.
// 16 rows/CTA. S[16x1032] smem; K/V 128-kv double-buffered chunks.
// Softmax: single pass (no max), P tf32-rounded on write.
// ---------------------------------------------------------------------------
#define SS_LD 1032
#define CH_F (128 * 36)
#define SMEM_ATTN_F (16 * SS_LD + 2 * CH_F + 16 * 36 + 32 + 64 + 16 + 16 + 1024)

__global__ __launch_bounds__(256, 2)
void attn_kernel()
{
    extern __shared__ float sm[];
    float* sS  = sm;                          // 16512
    float* sKV = sS + 16 * SS_LD;             // 9216 (dbuf; later AV reduce)
    float* sQ  = sKV + 2 * CH_F;              // 576
    float* sqe = sQ + 16 * 36;                // 32
    float* sVE = sqe + 32;                    // 64
    float* srs = sVE + 64;                    // 16
    float* srw = srs + 16;                    // 16
    unsigned* sAdj = (unsigned*)(srw + 16);   // 512
    unsigned* sTyp = sAdj + 512;              // 512

    const int tid = threadIdx.x;
    const int h = blockIdx.y;
    const int b0 = blockIdx.x * 16;
    const int w = tid >> 5;

    // ---- stage Q, masks, VE ----
#pragma unroll
    for (int j = 0; j < 2; ++j) {
        int idx = tid + j * 256;
        sQ[(idx >> 5) * 36 + (idx & 31)] = g_Q[h * 32768 + (b0 + (idx >> 5)) * 32 + (idx & 31)];
    }
#pragma unroll
    for (int j = 0; j < 2; ++j) {
        int idx = tid + j * 256;
        sAdj[idx] = g_mba2[(b0 + (idx >> 5)) * 32 + (idx & 31)];
        sTyp[idx] = g_mbt2[(b0 + (idx >> 5)) * 32 + (idx & 31)];
    }
    if (tid < 64) sVE[tid] = g_VE[(tid >> 5) * 256 + h * 32 + (tid & 31)];
    __syncthreads();

    // qe[row][t] = Q[row].KE[t]
    if (tid < 32) {
        int row = tid >> 1, t = tid & 1;
        float a = 0.f;
#pragma unroll
        for (int d = 0; d < 32; ++d) a += sQ[row * 36 + d] * g_KE[t * 256 + h * 32 + d];
        sqe[row * 2 + t] = a;
    }

    // ---- Q fragments (pre-rounded tf32) ----
    FragA af[4];
#pragma unroll
    for (int kt = 0; kt < 4; ++kt)
        wmma::load_matrix_sync(af[kt], &sQ[kt * 8], 36);

    // ---- SCORE: stream K chunks (dbuf -> one sync per chunk) ----
    const float4* gK = reinterpret_cast<const float4*>(g_K + h * 32768);
    float4 pf0, pf1, pf2, pf3;
    pf0 = __ldg(gK + tid);
    pf1 = __ldg(gK + tid + 256);
    pf2 = __ldg(gK + tid + 512);
    pf3 = __ldg(gK + tid + 768);

    for (int kc = 0; kc < 8; ++kc) {
        float* buf = sKV + (kc & 1) * CH_F;
        {
            int i0 = tid, i1 = tid + 256, i2 = tid + 512, i3 = tid + 768;
            *reinterpret_cast<float4*>(&buf[(i0 >> 3) * 36 + (i0 & 7) * 4]) = pf0;
            *reinterpret_cast<float4*>(&buf[(i1 >> 3) * 36 + (i1 & 7) * 4]) = pf1;
            *reinterpret_cast<float4*>(&buf[(i2 >> 3) * 36 + (i2 & 7) * 4]) = pf2;
            *reinterpret_cast<float4*>(&buf[(i3 >> 3) * 36 + (i3 & 7) * 4]) = pf3;
        }
        __syncthreads();
        if (kc < 7) {
            const float4* src = gK + (kc + 1) * 1024;
            pf0 = __ldg(src + tid);
            pf1 = __ldg(src + tid + 256);
            pf2 = __ldg(src + tid + 512);
            pf3 = __ldg(src + tid + 768);
        }
        FragC c0;
        wmma::fill_fragment(c0, 0.f);
#pragma unroll
        for (int kt = 0; kt < 4; ++kt) {
            FragBc bf;
            wmma::load_matrix_sync(bf, &buf[w * 16 * 36 + kt * 8], 36);
            wmma::mma_sync(c0, af[kt], bf, c0);
        }
        wmma::store_matrix_sync(&sS[kc * 128 + w * 16], c0, SS_LD, wmma::mem_row_major);
        // no trailing sync (double-buffered)
    }
    __syncthreads();   // all S written before softmax

    // ---- V chunk 0 prefetch ----
    const float4* gV = reinterpret_cast<const float4*>(g_V + h * 32768);
    pf0 = __ldg(gV + tid);
    pf1 = __ldg(gV + tid + 256);
    pf2 = __ldg(gV + tid + 512);
    pf3 = __ldg(gV + tid + 768);

    // ---- softmax: ONE pass, no max subtraction ----
    const int row = tid >> 4, c16 = tid & 15;
    const unsigned aw0 = sAdj[row * 32 + c16 * 2 + 0];
    const unsigned aw1 = sAdj[row * 32 + c16 * 2 + 1];
    const unsigned tw0 = sTyp[row * 32 + c16 * 2 + 0];
    const unsigned tw1 = sTyp[row * 32 + c16 * 2 + 1];
    const float qe0 = sqe[row * 2], qe1 = sqe[row * 2 + 1];
    float* rowp = sS + row * SS_LD + c16 * 64;

    float rs = 0.f, rw = 0.f;
#pragma unroll
    for (int jj = 0; jj < 16; ++jj) {
        int j = (jj + c16) & 15;              // lane stagger
        float4 s = *reinterpret_cast<float4*>(&rowp[j * 4]);
        unsigned a = (j & 8) ? aw1 : aw0;
        unsigned t = (j & 8) ? tw1 : tw0;
        int bb = (j & 7) * 4;
        float p0 = ((a >> (bb + 0)) & 1u) ? __expf(s.x + (((t >> (bb + 0)) & 1u) ? qe1 : qe0)) : 0.f;
        float p1 = ((a >> (bb + 1)) & 1u) ? __expf(s.y + (((t >> (bb + 1)) & 1u) ? qe1 : qe0)) : 0.f;
        float p2 = ((a >> (bb + 2)) & 1u) ? __expf(s.z + (((t >> (bb + 2)) & 1u) ? qe1 : qe0)) : 0.f;
        float p3 = ((a >> (bb + 3)) & 1u) ? __expf(s.w + (((t >> (bb + 3)) & 1u) ? qe1 : qe0)) : 0.f;
        rs += p0 + p1 + p2 + p3;
        if ((t >> (bb + 0)) & 1u) rw += p0;
        if ((t >> (bb + 1)) & 1u) rw += p1;
        if ((t >> (bb + 2)) & 1u) rw += p2;
        if ((t >> (bb + 3)) & 1u) rw += p3;
        s.x = wmma::__float_to_tf32(p0);      // pre-round P for the PV MMA
        s.y = wmma::__float_to_tf32(p1);
        s.z = wmma::__float_to_tf32(p2);
        s.w = wmma::__float_to_tf32(p3);
        *reinterpret_cast<float4*>(&rowp[j * 4]) = s;
    }
#pragma unroll
    for (int m = 8; m; m >>= 1) {
        rs += __shfl_xor_sync(0xffffffffu, rs, m);
        rw += __shfl_xor_sync(0xffffffffu, rw, m);
    }
    if (c16 == 0) { srs[row] = rs; srw[row] = rw; }
    __syncthreads();

    // ---- AV: warp w owns kv slice [w*16, w*16+16) of each chunk ----
    FragC oc[2];
    wmma::fill_fragment(oc[0], 0.f);
    wmma::fill_fragment(oc[1], 0.f);

    for (int kc = 0; kc < 8; ++kc) {
        float* buf = sKV + (kc & 1) * CH_F;
        {
            int i0 = tid, i1 = tid + 256, i2 = tid + 512, i3 = tid + 768;
            *reinterpret_cast<float4*>(&buf[(i0 >> 3) * 36 + (i0 & 7) * 4]) = pf0;
            *reinterpret_cast<float4*>(&buf[(i1 >> 3) * 36 + (i1 & 7) * 4]) = pf1;
            *reinterpret_cast<float4*>(&buf[(i2 >> 3) * 36 + (i2 & 7) * 4]) = pf2;
            *reinterpret_cast<float4*>(&buf[(i3 >> 3) * 36 + (i3 & 7) * 4]) = pf3;
        }
        __syncthreads();
        if (kc < 7) {
            const float4* src = gV + (kc + 1) * 1024;
            pf0 = __ldg(src + tid);
            pf1 = __ldg(src + tid + 256);
            pf2 = __ldg(src + tid + 512);
            pf3 = __ldg(src + tid + 768);
        }
#pragma unroll
        for (int kt2 = 0; kt2 < 2; ++kt2) {
            int kb = w * 16 + kt2 * 8;
            FragA pa;
            wmma::load_matrix_sync(pa, &sS[kc * 128 + kb], SS_LD);
            FragBr vb0, vb1;
            wmma::load_matrix_sync(vb0, &buf[kb * 36 + 0], 36);
            wmma::load_matrix_sync(vb1, &buf[kb * 36 + 16], 36);
            wmma::mma_sync(oc[0], pa, vb0, oc[0]);
            wmma::mma_sync(oc[1], pa, vb1, oc[1]);
        }
        // no trailing sync (double-buffered; red-store safety argued below)
    }

    // red = buf0 region; last buf0 reads were chunk 6 (all warps passed
    // chunk 7's leading sync, hence finished chunk 6); chunk-7 readers use buf1.
    float* red = sKV;   // 8 * 576 = 4608 = CH_F
    wmma::store_matrix_sync(&red[w * 576 + 0],  oc[0], 36, wmma::mem_row_major);
    wmma::store_matrix_sync(&red[w * 576 + 16], oc[1], 36, wmma::mem_row_major);
    __syncthreads();

#pragma unroll
    for (int i = 0; i < 2; ++i) {
        int o = tid + i * 256;
        int r = o >> 5, d = o & 31;
        float v = 0.f;
#pragma unroll
        for (int ww = 0; ww < 8; ++ww) v += red[ww * 576 + r * 36 + d];
        float st = srs[r], w1s = srw[r];
        float inv = st > 0.f ? 1.f / st : 0.f;
        v = v * inv + (st - w1s) * inv * sVE[d] + w1s * inv * sVE[32 + d];
        g_AO[(b0 + r) * 256 + h * 32 + d] = v;
    }
}

// ---------------------------------------------------------------------------
extern "C" void kernel_launch(void* const* d_in, const int* in_sizes, int n_in,
                              void* d_out, int out_size)
{
    const float* h_target = (const float*)d_in[0];
    const float* h_neigh  = (const float*)d_in[1];
    const int*   adjacency = (const int*)d_in[2];
    const int*   edge_types = (const int*)d_in[3];
    const float* Wq = (const float*)d_in[4];
    const float* bq = (const float*)d_in[5];
    const float* Wk = (const float*)d_in[6];
    const float* bk = (const float*)d_in[7];
    const float* Wv = (const float*)d_in[8];
    const float* bv = (const float*)d_in[9];
    const float* Wo = (const float*)d_in[10];
    const float* bo = (const float*)d_in[11];
    const float* E  = (const float*)d_in[12];
    float* out = (float*)d_out;

    const int attn_smem = SMEM_ATTN_F * 4;   // 109,824 B
    static int smem_set = 0;
    if (!smem_set) {
        cudaFuncSetAttribute(attn_kernel, cudaFuncAttributeMaxDynamicSharedMemorySize,
                             attn_smem);
        smem_set = 1;
    }

    prep_kernel<<<516, 256>>>(h_target, h_neigh, Wq, bq, Wk, bk, Wv, bv, E,
                              adjacency, edge_types);
    attn_kernel<<<dim3(64, 8), 256, attn_smem>>>();
    proj_kernel<<<dim3(32, 4), 256>>>(Wo, bo, out);
}